// round 9
// baseline (speedup 1.0000x reference)
#include <cuda_runtime.h>

#define B_ 64
#define N_ 1024
#define M_ 1024
#define Q_ 256          // float4 quads per row
#define QQ 64           // quads per quarter (per warp)
#define EPSF 1e-4f
#define NT 128          // 4 warps per block
#define RG 8            // rows per item
#define NG 128          // N_/RG
#define UH 2            // quads per lane per quarter

__device__ float g_part[(size_t)B_ * NG * M_];
__device__ float g_c[B_ * M_];
__device__ unsigned g_ctr[8];
__device__ unsigned g_arrive;
__device__ volatile unsigned g_release;

__device__ __forceinline__ void grid_sync(unsigned nb) {
    __syncthreads();
    if (threadIdx.x == 0) {
        __threadfence();
        unsigned gen = g_release;
        __threadfence();
        if (atomicAdd(&g_arrive, 1) == nb - 1) {
            g_arrive = 0;
            __threadfence();
            g_release = gen + 1;
        } else {
            while (g_release == gen) __nanosleep(64);
        }
    }
    __syncthreads();
}

__device__ __forceinline__ float warp_sum(float v) {
#pragma unroll
    for (int o = 16; o; o >>= 1) v += __shfl_xor_sync(0xffffffffu, v, o);
    return v;
}
__device__ __forceinline__ void warp_sum2(float& a, float& b) {
#pragma unroll
    for (int o = 16; o; o >>= 1) {
        a += __shfl_xor_sync(0xffffffffu, a, o);
        b += __shfl_xor_sync(0xffffffffu, b, o);
    }
}

struct Shm {
    int sb[B_];            // batches sorted by nc desc (LPT)
    int vpre[B_ + 1];      // prefix of valid row-groups (sorted order)
    int snr[B_], snc[B_];
    int idx;               // block's current item
    float cs[4];           // per-warp quarter csum
    float rs[4][RG];       // per-warp quarter row sums
};

// ---------------------------------------------------------------------------
// phase0: iter-0 column partials over ALL rows. Warp-stolen (b, rg, quarter).
// ---------------------------------------------------------------------------
__device__ void phase0(const float4* __restrict__ s4, Shm* sh, int lane) {
    for (;;) {
        unsigned sv = 0;
        if (lane == 0) sv = atomicAdd(&g_ctr[0], 1u);
        int item = (int)__shfl_sync(0xffffffffu, sv, 0);
        if (item >= B_ * NG * 4) break;
        int b = sh->sb[item >> 9];
        int rem = item & 511;
        int rg = rem >> 2, qi = rem & 3;
        int nq = (sh->snc[b] + 3) >> 2;
        int qoff = qi * QQ;
        if (qoff >= nq) continue;
        const float4* sp = s4 + (size_t)(b * N_ + rg * RG) * Q_ + qoff;
        float4 acc[UH];
#pragma unroll
        for (int u = 0; u < UH; u++) acc[u] = make_float4(0.f, 0.f, 0.f, 0.f);
        for (int r = 0; r < RG; r += 2) {
#pragma unroll
            for (int u = 0; u < UH; u++) {
                if (qoff + lane + 32 * u < nq) {
                    float4 v0 = __ldg(sp + r * Q_ + lane + 32 * u);
                    float4 v1 = __ldg(sp + (r + 1) * Q_ + lane + 32 * u);
                    acc[u].x += v0.x + v1.x; acc[u].y += v0.y + v1.y;
                    acc[u].z += v0.z + v1.z; acc[u].w += v0.w + v1.w;
                }
            }
        }
        float4* pp = reinterpret_cast<float4*>(g_part) +
                     (size_t)(b * NG + rg) * Q_ + qoff;
#pragma unroll
        for (int u = 0; u < UH; u++)
            if (qoff + lane + 32 * u < nq) __stcg(pp + lane + 32 * u, acc[u]);
    }
}

// ---------------------------------------------------------------------------
// finalize: c_j = 1/sum(group partials), masked; 8-way MLP, fixed order.
// ---------------------------------------------------------------------------
template <int FIRST>
__device__ void finalize_phase(const Shm* sh, int gtid, int gthreads) {
    for (int t = gtid; t < B_ * M_; t += gthreads) {
        int b = t >> 10, j = t & (M_ - 1);
        if (j >= sh->snc[b]) { __stcg(&g_c[t], 0.f); continue; }
        int G = FIRST ? NG : min(NG, (sh->snr[b] + RG - 1) / RG);
        const float* pp = g_part + (size_t)b * NG * M_ + j;
        float a[8];
#pragma unroll
        for (int k = 0; k < 8; k++) a[k] = 0.f;
        int g = 0;
        for (; g + 8 <= G; g += 8) {
#pragma unroll
            for (int k = 0; k < 8; k++)
                a[k] += __ldcg(pp + (size_t)(g + k) * M_);
        }
        for (; g < G; g++) a[0] += __ldcg(pp + (size_t)g * M_);
        float sum = (((a[0] + a[1]) + (a[2] + a[3])) +
                     ((a[4] + a[5]) + (a[6] + a[7]))) +
                    (FIRST ? (float)N_ * EPSF : 0.f);
        __stcg(&g_c[t], sum > 0.f ? __fdividef(1.f, sum) : 0.f);
    }
}

// ---------------------------------------------------------------------------
// Fused row+col pass. Block item = (batch, 8 rows); warp owns a col quarter.
// Loop1: row dots -> smem. One sync. Loop2: ri recomputed from smem per row,
// rows reloaded (L1 hit), column partials accumulated and written.
// eps folded: rowsum = dot(v,c)+eps*csum ; partial = sum v*ri + eps*sum(ri).
// ---------------------------------------------------------------------------
__device__ void fused_pass(const float4* __restrict__ s4, Shm* sh,
                           unsigned* ctr) {
    const int tid = threadIdx.x, lane = tid & 31, w = tid >> 5;
    const int qoff = w * QQ;
    const int count = sh->vpre[B_];
    for (;;) {
        __syncthreads();                       // protect idx/cs/rs reuse
        if (tid == 0) sh->idx = (int)atomicAdd(ctr, 1u);
        __syncthreads();
        int idx = sh->idx;
        if (idx >= count) break;
        int lo = 0, hi = B_;
        while (hi - lo > 1) {
            int mid = (lo + hi) >> 1;
            if (sh->vpre[mid] <= idx) lo = mid; else hi = mid;
        }
        int b = sh->sb[lo], rg = idx - sh->vpre[lo];
        int nr = sh->snr[b], nq = (sh->snc[b] + 3) >> 2;
        int i0 = rg * RG, rows = min(RG, nr - i0);
        const float4* cp = reinterpret_cast<const float4*>(g_c) + b * Q_ + qoff;
        const float4* sp = s4 + (size_t)(b * N_ + i0) * Q_ + qoff;
        float4 c[UH];
        float csl = 0.f;
#pragma unroll
        for (int u = 0; u < UH; u++) {
            c[u] = make_float4(0.f, 0.f, 0.f, 0.f);
            if (qoff + lane + 32 * u < nq) c[u] = __ldcg(cp + lane + 32 * u);
            csl += (c[u].x + c[u].y) + (c[u].z + c[u].w);
        }
        csl = warp_sum(csl);
        if (lane == 0) sh->cs[w] = csl;
        int r = 0;
        for (; r + 2 <= rows; r += 2) {
            float rs0 = 0.f, rs1 = 0.f;
#pragma unroll
            for (int u = 0; u < UH; u++) {
                if (qoff + lane + 32 * u < nq) {
                    float4 v0 = __ldg(sp + r * Q_ + lane + 32 * u);
                    float4 v1 = __ldg(sp + (r + 1) * Q_ + lane + 32 * u);
                    rs0 += (v0.x * c[u].x + v0.y * c[u].y) +
                           (v0.z * c[u].z + v0.w * c[u].w);
                    rs1 += (v1.x * c[u].x + v1.y * c[u].y) +
                           (v1.z * c[u].z + v1.w * c[u].w);
                }
            }
            warp_sum2(rs0, rs1);
            if (lane == 0) { sh->rs[w][r] = rs0; sh->rs[w][r + 1] = rs1; }
        }
        if (r < rows) {
            float rs0 = 0.f;
#pragma unroll
            for (int u = 0; u < UH; u++)
                if (qoff + lane + 32 * u < nq) {
                    float4 v0 = __ldg(sp + r * Q_ + lane + 32 * u);
                    rs0 += (v0.x * c[u].x + v0.y * c[u].y) +
                           (v0.z * c[u].z + v0.w * c[u].w);
                }
            rs0 = warp_sum(rs0);
            if (lane == 0) sh->rs[w][r] = rs0;
        }
        __syncthreads();
        float ecs = EPSF * ((sh->cs[0] + sh->cs[1]) + (sh->cs[2] + sh->cs[3]));
        float4 acc[UH];
#pragma unroll
        for (int u = 0; u < UH; u++) acc[u] = make_float4(0.f, 0.f, 0.f, 0.f);
        float rsum = 0.f;
        for (int rr = 0; rr < rows; rr++) {
            float t = ((sh->rs[0][rr] + sh->rs[1][rr]) +
                       (sh->rs[2][rr] + sh->rs[3][rr])) + ecs;
            float ri = t > 0.f ? __fdividef(1.f, t) : 0.f;
            rsum += ri;
#pragma unroll
            for (int u = 0; u < UH; u++) {
                if (qoff + lane + 32 * u < nq) {
                    float4 v = __ldg(sp + rr * Q_ + lane + 32 * u);  // L1 hit
                    acc[u].x += v.x * ri; acc[u].y += v.y * ri;
                    acc[u].z += v.z * ri; acc[u].w += v.w * ri;
                }
            }
        }
        float er = EPSF * rsum;
        float4* pp = reinterpret_cast<float4*>(g_part) +
                     (size_t)(b * NG + rg) * Q_ + qoff;
#pragma unroll
        for (int u = 0; u < UH; u++)
            if (qoff + lane + 32 * u < nq) {
                float4 o;
                o.x = acc[u].x + er; o.y = acc[u].y + er;
                o.z = acc[u].z + er; o.w = acc[u].w + er;
                __stcg(pp + lane + 32 * u, o);
            }
    }
}

// ---------------------------------------------------------------------------
// Final pass: iter-9 row norm + masked output (streaming stores). Block item
// over ALL (b, rg); invalid groups are pure zero-fill.
// ---------------------------------------------------------------------------
__device__ void final_pass(const float4* __restrict__ s4,
                           float4* __restrict__ o4, Shm* sh) {
    const int tid = threadIdx.x, lane = tid & 31, w = tid >> 5;
    const int qoff = w * QQ;
    const float4 z = make_float4(0.f, 0.f, 0.f, 0.f);
    for (;;) {
        __syncthreads();
        if (tid == 0) sh->idx = (int)atomicAdd(&g_ctr[5], 1u);
        __syncthreads();
        int idx = sh->idx;
        if (idx >= B_ * NG) break;
        int b = idx >> 7, rg = idx & (NG - 1);
        int nr = sh->snr[b];
        int i0 = rg * RG;
        float4* op = o4 + (size_t)(b * N_ + i0) * Q_ + qoff;
        if (i0 >= nr) {                       // uniform per block
            for (int r = 0; r < RG; r++)
#pragma unroll
                for (int u = 0; u < UH; u++)
                    __stcs(op + r * Q_ + lane + 32 * u, z);
            continue;
        }
        int nq = (sh->snc[b] + 3) >> 2;
        int rows = min(RG, nr - i0);
        const float4* cp = reinterpret_cast<const float4*>(g_c) + b * Q_ + qoff;
        const float4* sp = s4 + (size_t)(b * N_ + i0) * Q_ + qoff;
        float4 c[UH];
        float csl = 0.f;
#pragma unroll
        for (int u = 0; u < UH; u++) {
            c[u] = z;
            if (qoff + lane + 32 * u < nq) c[u] = __ldcg(cp + lane + 32 * u);
            csl += (c[u].x + c[u].y) + (c[u].z + c[u].w);
        }
        csl = warp_sum(csl);
        if (lane == 0) sh->cs[w] = csl;
        int r = 0;
        for (; r + 2 <= rows; r += 2) {
            float rs0 = 0.f, rs1 = 0.f;
#pragma unroll
            for (int u = 0; u < UH; u++) {
                if (qoff + lane + 32 * u < nq) {
                    float4 v0 = __ldg(sp + r * Q_ + lane + 32 * u);
                    float4 v1 = __ldg(sp + (r + 1) * Q_ + lane + 32 * u);
                    rs0 += (v0.x * c[u].x + v0.y * c[u].y) +
                           (v0.z * c[u].z + v0.w * c[u].w);
                    rs1 += (v1.x * c[u].x + v1.y * c[u].y) +
                           (v1.z * c[u].z + v1.w * c[u].w);
                }
            }
            warp_sum2(rs0, rs1);
            if (lane == 0) { sh->rs[w][r] = rs0; sh->rs[w][r + 1] = rs1; }
        }
        if (r < rows) {
            float rs0 = 0.f;
#pragma unroll
            for (int u = 0; u < UH; u++)
                if (qoff + lane + 32 * u < nq) {
                    float4 v0 = __ldg(sp + r * Q_ + lane + 32 * u);
                    rs0 += (v0.x * c[u].x + v0.y * c[u].y) +
                           (v0.z * c[u].z + v0.w * c[u].w);
                }
            rs0 = warp_sum(rs0);
            if (lane == 0) sh->rs[w][r] = rs0;
        }
        __syncthreads();
        float ecs = EPSF * ((sh->cs[0] + sh->cs[1]) + (sh->cs[2] + sh->cs[3]));
        for (int rr = 0; rr < RG; rr++) {
            if (rr < rows) {
                float t = ((sh->rs[0][rr] + sh->rs[1][rr]) +
                           (sh->rs[2][rr] + sh->rs[3][rr])) + ecs;
                float ri = t > 0.f ? __fdividef(1.f, t) : 0.f;
#pragma unroll
                for (int u = 0; u < UH; u++) {
                    float4 o = z;
                    if (qoff + lane + 32 * u < nq) {
                        float4 v = __ldg(sp + rr * Q_ + lane + 32 * u); // L1 hit
                        o.x = (v.x + EPSF) * ri * c[u].x;  // c==0 past nc
                        o.y = (v.y + EPSF) * ri * c[u].y;
                        o.z = (v.z + EPSF) * ri * c[u].z;
                        o.w = (v.w + EPSF) * ri * c[u].w;
                    }
                    __stcs(op + rr * Q_ + lane + 32 * u, o);
                }
            } else {
#pragma unroll
                for (int u = 0; u < UH; u++)
                    __stcs(op + rr * Q_ + lane + 32 * u, z);
            }
        }
    }
}

// ---------------------------------------------------------------------------
__global__ void __launch_bounds__(NT, 6)
sinkhorn_kernel(const float* __restrict__ s, const int* __restrict__ nrows,
                const int* __restrict__ ncols, float* __restrict__ out) {
    __shared__ Shm shm;
    const int tid = threadIdx.x;
    const int lane = tid & 31;
    const unsigned nb = gridDim.x;

    if (tid < B_) {
        shm.snr[tid] = __ldg(nrows + tid);
        shm.snc[tid] = __ldg(ncols + tid);
    }
    __syncthreads();
    if (tid < B_) {                     // rank sort by nc desc (LPT order)
        int myc = shm.snc[tid];
        int rank = 0;
        for (int j = 0; j < B_; j++) {
            int cj = shm.snc[j];
            rank += (cj > myc) || (cj == myc && j < tid);
        }
        shm.sb[rank] = tid;
    }
    __syncthreads();
    if (tid <= B_) {                    // prefix of valid row-groups
        int a = 0;
        for (int k = 0; k < tid; k++)
            a += (shm.snr[shm.sb[k]] + RG - 1) / RG;
        shm.vpre[tid] = a;
    }
    __syncthreads();

    const float4* s4 = reinterpret_cast<const float4*>(s);
    float4* o4 = reinterpret_cast<float4*>(out);
    const int gtid = blockIdx.x * NT + tid;
    const int gthreads = nb * NT;

    phase0(s4, &shm, lane);             // iter 0 column partials
    grid_sync(nb);
    finalize_phase<1>(&shm, gtid, gthreads);
    // safe reset: phase0 ctr done; fused/final ctrs not used until after sync
    if (blockIdx.x == 0 && tid < 8) g_ctr[tid] = 0;
    grid_sync(nb);

#pragma unroll 1
    for (int k = 0; k < 4; k++) {       // iters 1..8
        fused_pass(s4, &shm, &g_ctr[1 + k]);
        grid_sync(nb);
        finalize_phase<0>(&shm, gtid, gthreads);
        grid_sync(nb);
    }

    final_pass(s4, o4, &shm);           // iter 9 + masked output
}

extern "C" void kernel_launch(void* const* d_in, const int* in_sizes, int n_in,
                              void* d_out, int out_size) {
    const float* s   = (const float*)d_in[0];
    const int* nrows = (const int*)d_in[1];
    const int* ncols = (const int*)d_in[2];
    float* out       = (float*)d_out;

    int dev = 0;
    cudaGetDevice(&dev);
    int sms = 0;
    cudaDeviceGetAttribute(&sms, cudaDevAttrMultiProcessorCount, dev);
    int bpm = 0;
    cudaOccupancyMaxActiveBlocksPerMultiprocessor(&bpm, sinkhorn_kernel, NT, 0);
    int grid = sms * bpm;
    if (grid < 1) grid = 1;

    sinkhorn_kernel<<<grid, NT>>>(s, nrows, ncols, out);
}